// round 1
// baseline (speedup 1.0000x reference)
#include <cuda_runtime.h>

#define B_TOT    131072
#define NREAL    32
#define NCAT     32
#define DIN      128
#define SDIM     64
#define ROWS     128
#define NTHREADS 256
#define HALF_LOG2PI 0.9189385332046727f

#define PADR 129
#define YS_OFF   0
#define ST_OFF   (YS_OFF + DIN*PADR)
#define EPS_OFF  (ST_OFF + 32*PADR)
#define MISS_OFF (EPS_OFF + 32*PADR)
#define SAMP_OFF (MISS_OFF + 64*PADR)
#define MPZ_OFF  (SAMP_OFF + ROWS*65)
#define LP_OFF   (MPZ_OFF + ROWS*65)
#define SMEM_FLOATS (LP_OFF + ROWS)
#define SMEM_BYTES  (SMEM_FLOATS*4)

// Repacked W_cat: [d][f][8] (7 weights + zero pad) so the inner loop does
// 2x LDG.128 warp-uniform broadcast instead of 7 scalar strided loads.
__device__ float4 g_Wc[DIN*NCAT*2];

__global__ void repack_Wcat(const float* __restrict__ Wc) {
    int idx = blockIdx.x*blockDim.x + threadIdx.x;   // idx = d*32 + f
    if (idx >= DIN*NCAT) return;
    int d = idx >> 5, f = idx & 31;
    const float* src = Wc + (f*DIN + d)*7;
    g_Wc[idx*2]   = make_float4(src[0], src[1], src[2], src[3]);
    g_Wc[idx*2+1] = make_float4(src[4], src[5], src[6], 0.0f);
}

// -log(u) for u in [1e-6, 1-1e-6], accurate near u->1 where __logf's
// absolute error (~2^-21) would be catastrophically amplified.
__device__ __forceinline__ float neg_log_u(float u) {
    float v = 1.0f - u;                       // exact for u >= 0.5
    if (v < 0.0078125f)
        return v*(1.0f + v*(0.5f + v*(1.0f/3.0f)));   // rel err <= v^3/4 < 2e-7
    return -__logf(u);
}

__global__ __launch_bounds__(NTHREADS, 1)
void hivae_kernel(const float* __restrict__ y,   const float* __restrict__ s,
                  const float* __restrict__ st,  const float* __restrict__ Wz,
                  const float* __restrict__ bz,  const float* __restrict__ Wr,
                  const float* __restrict__ br,  const float* __restrict__ bc,
                  const float* __restrict__ eps, const float* __restrict__ gum,
                  const int*   __restrict__ miss, float* __restrict__ out)
{
    extern __shared__ float sm[];
    const int tid = threadIdx.x;
    const int rb  = blockIdx.x * ROWS;

    // ---------------- stage (transposed, conflict-free pad 129) -------------
    for (int idx = tid; idx < ROWS*DIN; idx += NTHREADS) {
        int row = idx >> 7, c = idx & 127;
        float v = (c < 64) ? y[(rb+row)*64 + c] : s[(rb+row)*64 + (c-64)];
        sm[YS_OFF + c*PADR + row] = v;
    }
    for (int idx = tid; idx < ROWS*32; idx += NTHREADS) {
        int row = idx >> 5, c = idx & 31;
        sm[ST_OFF  + c*PADR + row] = st[(rb+row)*288 + c];
        sm[EPS_OFF + c*PADR + row] = eps[(rb+row)*32 + c];
    }
    for (int idx = tid; idx < ROWS*64; idx += NTHREADS) {
        int row = idx >> 6, c = idx & 63;
        sm[MISS_OFF + c*PADR + row] = (float)miss[(rb+row)*64 + c];
    }
    if (tid < ROWS) sm[LP_OFF + tid] = 0.0f;
    __syncthreads();

    const int warp = tid >> 5, lane = tid & 31;

    // ---------------- categorical: 4 rows x 1 feature per thread ------------
    for (int j = 0; j < 4; j++) {
        const int f = warp*4 + j;
        float acc[4][7];
        #pragma unroll
        for (int i = 0; i < 4; i++)
            #pragma unroll
            for (int o = 0; o < 7; o++) acc[i][o] = bc[f*7 + o];

        #pragma unroll 2
        for (int d = 0; d < DIN; d++) {
            float a[4];
            #pragma unroll
            for (int i = 0; i < 4; i++) a[i] = sm[YS_OFF + d*PADR + lane + i*32];
            float4 wlo = g_Wc[(d*NCAT + f)*2];
            float4 whi = g_Wc[(d*NCAT + f)*2 + 1];
            #pragma unroll
            for (int i = 0; i < 4; i++) {
                acc[i][0] += a[i]*wlo.x; acc[i][1] += a[i]*wlo.y;
                acc[i][2] += a[i]*wlo.z; acc[i][3] += a[i]*wlo.w;
                acc[i][4] += a[i]*whi.x; acc[i][5] += a[i]*whi.y;
                acc[i][6] += a[i]*whi.z;
            }
        }
        #pragma unroll
        for (int i = 0; i < 4; i++) {
            const int r = i*32 + lane;
            const int grow = rb + r;
            float lpi[8];
            lpi[0] = 0.0f;
            #pragma unroll
            for (int k = 1; k < 8; k++) lpi[k] = acc[i][k-1];
            float m = lpi[0];
            #pragma unroll
            for (int k = 1; k < 8; k++) m = fmaxf(m, lpi[k]);
            float se = 0.0f;
            #pragma unroll
            for (int k = 0; k < 8; k++) se += __expf(lpi[k] - m);
            float lse = m + __logf(se);

            const float4* dc = (const float4*)(st + (size_t)grow*288 + 32 + f*8);
            float4 d0 = dc[0], d1 = dc[1];
            float lp = d0.x*(lpi[0]-lse) + d0.y*(lpi[1]-lse) + d0.z*(lpi[2]-lse) + d0.w*(lpi[3]-lse)
                     + d1.x*(lpi[4]-lse) + d1.y*(lpi[5]-lse) + d1.z*(lpi[6]-lse) + d1.w*(lpi[7]-lse);
            lp *= sm[MISS_OFF + (32+f)*PADR + r];
            atomicAdd(&sm[LP_OFF + r], lp);

            const float4* gu = (const float4*)(gum + (size_t)grow*256 + f*8);
            float4 g0 = gu[0], g1 = gu[1];
            float uv[8] = {g0.x,g0.y,g0.z,g0.w,g1.x,g1.y,g1.z,g1.w};
            float best = -1e30f; int bi = 0;
            #pragma unroll
            for (int k = 0; k < 8; k++) {
                float u  = fminf(fmaxf(uv[k], 1e-6f), 1.0f - 1e-6f);
                float gk = -__logf(neg_log_u(u));
                float val = lpi[k] + gk;
                if (val > best) { best = val; bi = k; }
            }
            sm[SAMP_OFF + r*65 + 32 + f] = (float)bi;
        }
    }

    // ---------------- real: 4 rows x 1 feature per thread -------------------
    for (int j = 0; j < 4; j++) {
        const int f = warp*4 + j;
        float am[4], al[4];
        #pragma unroll
        for (int i = 0; i < 4; i++) { am[i] = br[f*2]; al[i] = br[f*2 + 1]; }
        const float2* wr2 = (const float2*)Wr;
        #pragma unroll 4
        for (int d = 0; d < DIN; d++) {
            float2 w = wr2[f*DIN + d];
            #pragma unroll
            for (int i = 0; i < 4; i++) {
                float a = sm[YS_OFF + d*PADR + lane + i*32];
                am[i] += a*w.x; al[i] += a*w.y;
            }
        }
        #pragma unroll
        for (int i = 0; i < 4; i++) {
            const int r  = i*32 + lane;
            float mu = am[i];
            float lv = fminf(fmaxf(al[i], -10.0f), 10.0f);
            float x  = sm[ST_OFF + f*PADR + r];
            float mi = sm[MISS_OFF + f*PADR + r];
            float dmu = x - mu;
            float lp = (-0.5f*dmu*dmu*__expf(-lv) - 0.5f*lv - HALF_LOG2PI) * mi;
            atomicAdd(&sm[LP_OFF + r], lp);
            float sd = fmaxf(__expf(0.5f*lv), 1e-6f);
            sm[SAMP_OFF + r*65 + f] = mu + sd * sm[EPS_OFF + f*PADR + r];
        }
    }

    // ---------------- mean_pz: 4 rows x 8 outputs per thread ----------------
    {
        const int zb = warp*8;
        float acc[4][8];
        #pragma unroll
        for (int i = 0; i < 4; i++)
            #pragma unroll
            for (int jj = 0; jj < 8; jj++) acc[i][jj] = bz[zb + jj];
        #pragma unroll 2
        for (int d = 0; d < SDIM; d++) {
            float a[4];
            #pragma unroll
            for (int i = 0; i < 4; i++) a[i] = sm[YS_OFF + (64+d)*PADR + lane + i*32];
            #pragma unroll
            for (int jj = 0; jj < 8; jj++) {
                float w = Wz[(zb+jj)*SDIM + d];
                #pragma unroll
                for (int i = 0; i < 4; i++) acc[i][jj] += a[i]*w;
            }
        }
        #pragma unroll
        for (int i = 0; i < 4; i++) {
            const int r = i*32 + lane;
            #pragma unroll
            for (int jj = 0; jj < 8; jj++)
                sm[MPZ_OFF + r*65 + zb + jj] = acc[i][jj];
        }
    }

    __syncthreads();

    // ---------------- coalesced store ---------------------------------------
    const long B64 = (long)B_TOT*64;
    for (int idx = tid; idx < ROWS*64; idx += NTHREADS) {
        int row = idx >> 6, c = idx & 63;
        long g = (long)(rb+row)*64 + c;
        out[g]        = sm[SAMP_OFF + row*65 + c];   // samples_out
        out[B64 + g]  = sm[MPZ_OFF  + row*65 + c];   // mean_pz
        out[2*B64 + g] = 0.0f;                       // log_var_pz
    }
    if (tid < ROWS) out[3*B64 + rb + tid] = sm[LP_OFF + tid];  // log_p_x_sum
}

extern "C" void kernel_launch(void* const* d_in, const int* in_sizes, int n_in,
                              void* d_out, int out_size)
{
    const float* y    = (const float*)d_in[0];
    const float* s    = (const float*)d_in[1];
    const float* st   = (const float*)d_in[2];
    const float* Wz   = (const float*)d_in[3];
    const float* bz   = (const float*)d_in[4];
    const float* Wr   = (const float*)d_in[5];
    const float* br   = (const float*)d_in[6];
    const float* Wc   = (const float*)d_in[7];
    const float* bc   = (const float*)d_in[8];
    const float* eps  = (const float*)d_in[9];
    const float* gum  = (const float*)d_in[10];
    const int*   miss = (const int*)d_in[11];
    float* out = (float*)d_out;

    cudaFuncSetAttribute(hivae_kernel,
                         cudaFuncAttributeMaxDynamicSharedMemorySize, SMEM_BYTES);
    repack_Wcat<<<(DIN*NCAT + 255)/256, 256>>>(Wc);
    hivae_kernel<<<B_TOT/ROWS, NTHREADS, SMEM_BYTES>>>(
        y, s, st, Wz, bz, Wr, br, bc, eps, gum, miss, out);
}

// round 2
// speedup vs baseline: 1.2776x; 1.2776x over previous
#include <cuda_runtime.h>

#define B_TOT    131072
#define DIN      128
#define SDIM     64
#define ROWS     64
#define NTHREADS 256
#define PAD      65
#define HALF_LOG2PI 0.9189385332046727f

// smem float offsets
#define YS_OFF   0                      // 128*65 = 8320
#define ST_OFF   (YS_OFF + DIN*PAD)     // 32*65 = 2080
#define EPS_OFF  (ST_OFF + 32*PAD)      // 2080
#define SAMP_OFF (EPS_OFF + 32*PAD)     // 64*65 = 4160
#define LP_OFF   (SAMP_OFF + ROWS*PAD)  // 64
#define MISSB_OFF_BYTES ((LP_OFF + ROWS)*4)   // char region: 64 cols * 68 stride
#define SMEM_BYTES (MISSB_OFF_BYTES + 64*68)  // = 71168 B -> 3 CTAs/SM

// Repacked weights (device scratch, filled by prep kernel)
__device__ float4 g_Wc [DIN*32*2];   // [d][f][8] (7 + pad)
__device__ float2 g_Wr2[DIN*32];     // [d][f] (mean_w, logvar_w)
__device__ float  g_Wzt[SDIM*64];    // [d][z]

__global__ void repack_kernel(const float* __restrict__ Wc,
                              const float* __restrict__ Wr,
                              const float* __restrict__ Wz) {
    int idx = blockIdx.x*blockDim.x + threadIdx.x;
    if (idx >= DIN*32) return;
    int d = idx >> 5, f = idx & 31;
    const float* src = Wc + (f*DIN + d)*7;
    g_Wc[idx*2]   = make_float4(src[0], src[1], src[2], src[3]);
    g_Wc[idx*2+1] = make_float4(src[4], src[5], src[6], 0.0f);
    g_Wr2[d*32 + f] = make_float2(Wr[(f*DIN + d)*2], Wr[(f*DIN + d)*2 + 1]);
    int dz = idx >> 6, z = idx & 63;   // idx < 4096 covers 64x64
    g_Wzt[dz*64 + z] = Wz[z*SDIM + dz];
}

// -log(u), accurate near u->1 where __logf's absolute error would be amplified.
__device__ __forceinline__ float neg_log_u(float u) {
    float v = 1.0f - u;
    if (v < 0.0078125f)
        return v*(1.0f + v*(0.5f + v*(1.0f/3.0f)));
    return -__logf(u);
}

__global__ __launch_bounds__(NTHREADS, 3)
void hivae_kernel(const float* __restrict__ y,   const float* __restrict__ s,
                  const float* __restrict__ st,  const float* __restrict__ bz,
                  const float* __restrict__ br,  const float* __restrict__ bc,
                  const float* __restrict__ eps, const float* __restrict__ gum,
                  const int*   __restrict__ miss, float* __restrict__ out)
{
    extern __shared__ float sm[];
    char* smc = (char*)sm + MISSB_OFF_BYTES;
    const int tid = threadIdx.x;
    const int rb  = blockIdx.x * ROWS;

    // ---------------- stage ------------------------------------------------
    for (int idx = tid; idx < ROWS*DIN; idx += NTHREADS) {
        int row = idx >> 7, c = idx & 127;
        float v = (c < 64) ? y[(rb+row)*64 + c] : s[(rb+row)*64 + (c-64)];
        sm[YS_OFF + c*PAD + row] = v;
    }
    for (int idx = tid; idx < ROWS*32; idx += NTHREADS) {
        int row = idx >> 5, c = idx & 31;
        sm[ST_OFF  + c*PAD + row] = st[(rb+row)*288 + c];
        sm[EPS_OFF + c*PAD + row] = eps[(rb+row)*32 + c];
    }
    for (int idx = tid; idx < ROWS*64; idx += NTHREADS) {
        int row = idx >> 6, c = idx & 63;
        smc[c*68 + row] = (char)miss[(rb+row)*64 + c];
    }
    if (tid < ROWS) sm[LP_OFF + tid] = 0.0f;
    __syncthreads();

    const int warp = tid >> 5, lane = tid & 31;
    float lp_acc[2] = {0.0f, 0.0f};

    // -------- categorical: 2 feature-pairs x 2 rows per thread -------------
    #pragma unroll 1
    for (int jj = 0; jj < 2; jj++) {
        const int f0 = warp*4 + jj*2;
        float acc[2][2][7];
        #pragma unroll
        for (int ff = 0; ff < 2; ff++)
            #pragma unroll
            for (int o = 0; o < 7; o++) {
                float b = bc[(f0+ff)*7 + o];
                acc[0][ff][o] = b; acc[1][ff][o] = b;
            }
        #pragma unroll 4
        for (int d = 0; d < DIN; d++) {
            float a0 = sm[YS_OFF + d*PAD + lane];
            float a1 = sm[YS_OFF + d*PAD + lane + 32];
            const float4* wp = &g_Wc[(d*32 + f0)*2];
            float4 w00 = wp[0], w01 = wp[1], w10 = wp[2], w11 = wp[3];
            acc[0][0][0] += a0*w00.x; acc[0][0][1] += a0*w00.y;
            acc[0][0][2] += a0*w00.z; acc[0][0][3] += a0*w00.w;
            acc[0][0][4] += a0*w01.x; acc[0][0][5] += a0*w01.y;
            acc[0][0][6] += a0*w01.z;
            acc[0][1][0] += a0*w10.x; acc[0][1][1] += a0*w10.y;
            acc[0][1][2] += a0*w10.z; acc[0][1][3] += a0*w10.w;
            acc[0][1][4] += a0*w11.x; acc[0][1][5] += a0*w11.y;
            acc[0][1][6] += a0*w11.z;
            acc[1][0][0] += a1*w00.x; acc[1][0][1] += a1*w00.y;
            acc[1][0][2] += a1*w00.z; acc[1][0][3] += a1*w00.w;
            acc[1][0][4] += a1*w01.x; acc[1][0][5] += a1*w01.y;
            acc[1][0][6] += a1*w01.z;
            acc[1][1][0] += a1*w10.x; acc[1][1][1] += a1*w10.y;
            acc[1][1][2] += a1*w10.z; acc[1][1][3] += a1*w10.w;
            acc[1][1][4] += a1*w11.x; acc[1][1][5] += a1*w11.y;
            acc[1][1][6] += a1*w11.z;
        }
        #pragma unroll
        for (int i = 0; i < 2; i++) {
            #pragma unroll
            for (int ff = 0; ff < 2; ff++) {
                const int f = f0 + ff;
                const int r = i*32 + lane;
                const int grow = rb + r;
                float lpi[8];
                lpi[0] = 0.0f;
                #pragma unroll
                for (int k = 1; k < 8; k++) lpi[k] = acc[i][ff][k-1];
                float m = lpi[0];
                #pragma unroll
                for (int k = 1; k < 8; k++) m = fmaxf(m, lpi[k]);
                float se = 0.0f;
                #pragma unroll
                for (int k = 0; k < 8; k++) se += __expf(lpi[k] - m);
                float lse = m + __logf(se);

                const float4* dc = (const float4*)(st + (size_t)grow*288 + 32 + f*8);
                float4 d0 = dc[0], d1 = dc[1];
                float lp = d0.x*(lpi[0]-lse) + d0.y*(lpi[1]-lse) + d0.z*(lpi[2]-lse) + d0.w*(lpi[3]-lse)
                         + d1.x*(lpi[4]-lse) + d1.y*(lpi[5]-lse) + d1.z*(lpi[6]-lse) + d1.w*(lpi[7]-lse);
                lp_acc[i] += lp * (float)smc[(32+f)*68 + r];

                const float4* gu = (const float4*)(gum + (size_t)grow*256 + f*8);
                float4 g0 = gu[0], g1 = gu[1];
                float uv[8] = {g0.x,g0.y,g0.z,g0.w,g1.x,g1.y,g1.z,g1.w};
                float best = -1e30f; int bi = 0;
                #pragma unroll
                for (int k = 0; k < 8; k++) {
                    float u  = fminf(fmaxf(uv[k], 1e-6f), 1.0f - 1e-6f);
                    float gk = -__logf(neg_log_u(u));
                    float val = lpi[k] + gk;
                    if (val > best) { best = val; bi = k; }
                }
                sm[SAMP_OFF + r*PAD + 32 + f] = (float)bi;
            }
        }
    }

    // -------- real: 4 features x 2 rows per thread --------------------------
    {
        const int f0 = warp*4;
        float am[2][4], al[2][4];
        #pragma unroll
        for (int q = 0; q < 4; q++) {
            float bm = br[(f0+q)*2], bl = br[(f0+q)*2 + 1];
            am[0][q] = bm; am[1][q] = bm;
            al[0][q] = bl; al[1][q] = bl;
        }
        #pragma unroll 4
        for (int d = 0; d < DIN; d++) {
            float a0 = sm[YS_OFF + d*PAD + lane];
            float a1 = sm[YS_OFF + d*PAD + lane + 32];
            float4 wA = *(const float4*)&g_Wr2[d*32 + f0];
            float4 wB = *(const float4*)&g_Wr2[d*32 + f0 + 2];
            am[0][0] += a0*wA.x; al[0][0] += a0*wA.y;
            am[0][1] += a0*wA.z; al[0][1] += a0*wA.w;
            am[0][2] += a0*wB.x; al[0][2] += a0*wB.y;
            am[0][3] += a0*wB.z; al[0][3] += a0*wB.w;
            am[1][0] += a1*wA.x; al[1][0] += a1*wA.y;
            am[1][1] += a1*wA.z; al[1][1] += a1*wA.w;
            am[1][2] += a1*wB.x; al[1][2] += a1*wB.y;
            am[1][3] += a1*wB.z; al[1][3] += a1*wB.w;
        }
        #pragma unroll
        for (int i = 0; i < 2; i++) {
            const int r = i*32 + lane;
            #pragma unroll
            for (int q = 0; q < 4; q++) {
                const int f = f0 + q;
                float mu = am[i][q];
                float lv = fminf(fmaxf(al[i][q], -10.0f), 10.0f);
                float x  = sm[ST_OFF + f*PAD + r];
                float mi = (float)smc[f*68 + r];
                float dmu = x - mu;
                lp_acc[i] += (-0.5f*dmu*dmu*__expf(-lv) - 0.5f*lv - HALF_LOG2PI) * mi;
                float sd = fmaxf(__expf(0.5f*lv), 1e-6f);
                sm[SAMP_OFF + r*PAD + f] = mu + sd * sm[EPS_OFF + f*PAD + r];
            }
        }
    }
    atomicAdd(&sm[LP_OFF + lane],      lp_acc[0]);
    atomicAdd(&sm[LP_OFF + lane + 32], lp_acc[1]);

    // -------- mean_pz: 8 z-outputs x 2 rows, direct float4 stores -----------
    {
        const int zb = warp*8;
        const long B64 = (long)B_TOT*64;
        float az[2][8];
        #pragma unroll
        for (int j = 0; j < 8; j++) { float b = bz[zb+j]; az[0][j] = b; az[1][j] = b; }
        #pragma unroll 4
        for (int d = 0; d < SDIM; d++) {
            float a0 = sm[YS_OFF + (64+d)*PAD + lane];
            float a1 = sm[YS_OFF + (64+d)*PAD + lane + 32];
            float4 w0 = *(const float4*)&g_Wzt[d*64 + zb];
            float4 w1 = *(const float4*)&g_Wzt[d*64 + zb + 4];
            az[0][0] += a0*w0.x; az[0][1] += a0*w0.y; az[0][2] += a0*w0.z; az[0][3] += a0*w0.w;
            az[0][4] += a0*w1.x; az[0][5] += a0*w1.y; az[0][6] += a0*w1.z; az[0][7] += a0*w1.w;
            az[1][0] += a1*w0.x; az[1][1] += a1*w0.y; az[1][2] += a1*w0.z; az[1][3] += a1*w0.w;
            az[1][4] += a1*w1.x; az[1][5] += a1*w1.y; az[1][6] += a1*w1.z; az[1][7] += a1*w1.w;
        }
        #pragma unroll
        for (int i = 0; i < 2; i++) {
            const long grow = rb + i*32 + lane;
            *(float4*)&out[B64 + grow*64 + zb]     = make_float4(az[i][0],az[i][1],az[i][2],az[i][3]);
            *(float4*)&out[B64 + grow*64 + zb + 4] = make_float4(az[i][4],az[i][5],az[i][6],az[i][7]);
        }
    }

    __syncthreads();

    // -------- coalesced stores: samples, zeros, log_p_sum -------------------
    const long B64 = (long)B_TOT*64;
    const float4 z4 = make_float4(0.f,0.f,0.f,0.f);
    for (int idx = tid; idx < ROWS*16; idx += NTHREADS) {
        int row = idx >> 4, c = (idx & 15)*4;
        long g = (long)(rb+row)*64 + c;
        float4 v = make_float4(sm[SAMP_OFF + row*PAD + c],
                               sm[SAMP_OFF + row*PAD + c + 1],
                               sm[SAMP_OFF + row*PAD + c + 2],
                               sm[SAMP_OFF + row*PAD + c + 3]);
        *(float4*)&out[g] = v;
        *(float4*)&out[2*B64 + g] = z4;
    }
    if (tid < ROWS) out[3*B64 + rb + tid] = sm[LP_OFF + tid];
}

extern "C" void kernel_launch(void* const* d_in, const int* in_sizes, int n_in,
                              void* d_out, int out_size)
{
    const float* y    = (const float*)d_in[0];
    const float* s    = (const float*)d_in[1];
    const float* st   = (const float*)d_in[2];
    const float* Wz   = (const float*)d_in[3];
    const float* bz   = (const float*)d_in[4];
    const float* Wr   = (const float*)d_in[5];
    const float* br   = (const float*)d_in[6];
    const float* Wc   = (const float*)d_in[7];
    const float* bc   = (const float*)d_in[8];
    const float* eps  = (const float*)d_in[9];
    const float* gum  = (const float*)d_in[10];
    const int*   miss = (const int*)d_in[11];
    float* out = (float*)d_out;

    cudaFuncSetAttribute(hivae_kernel,
                         cudaFuncAttributeMaxDynamicSharedMemorySize, SMEM_BYTES);
    repack_kernel<<<16, 256>>>(Wc, Wr, Wz);
    hivae_kernel<<<B_TOT/ROWS, NTHREADS, SMEM_BYTES>>>(
        y, s, st, bz, br, bc, eps, gum, miss, out);
}

// round 4
// speedup vs baseline: 1.2948x; 1.0134x over previous
#include <cuda_runtime.h>

#define B_TOT    131072
#define DIN      128
#define SDIM     64
#define ROWS     64
#define NTHREADS 256
#define HALF_LOG2PI 0.9189385332046727f

// smem float offsets
#define YS_OFF   0                       // 128*65 = 8320 floats
#define TSE_OFF  (DIN*65)                // 4160 floats: T-buffer OR st/eps staging
#define ST2_OFF  TSE_OFF
#define EPS2_OFF (TSE_OFF + 32*65)
#define SAMP_OFF (TSE_OFF + 4160)        // 64*65 = 4160
#define LP_OFF   (SAMP_OFF + 64*65)      // 64
#define MISS_BYTE_OFF ((LP_OFF + 64)*4)
#define SMEM_BYTES (MISS_BYTE_OFF + 64*68)   // 71168 B -> 3 CTAs/SM

typedef unsigned long long u64;

// Repacked weights (prep kernel)
__device__ float4 g_Wc2[DIN*16*4];   // [d][fpair][8 f32x2: o0..o6,pad]
__device__ float2 g_Wr2[DIN*32];     // [d][f] (mean_w, logvar_w)
__device__ float  g_Wzt[SDIM*64];    // [d][z]
__device__ float2 g_bc2[16*8];       // cat bias pairs

__global__ void repack_kernel(const float* __restrict__ Wc,
                              const float* __restrict__ Wr,
                              const float* __restrict__ Wz,
                              const float* __restrict__ bc) {
    int idx = blockIdx.x*blockDim.x + threadIdx.x;
    if (idx < DIN*32) {
        int d = idx >> 5, f = idx & 31;
        g_Wr2[d*32 + f] = make_float2(Wr[(f*DIN + d)*2], Wr[(f*DIN + d)*2 + 1]);
        int dz = idx >> 6, z = idx & 63;
        g_Wzt[dz*64 + z] = Wz[z*SDIM + dz];
    }
    if (idx < DIN*16) {
        int d = idx >> 4, fp = idx & 15;
        const float* s0 = Wc + ((2*fp)*DIN + d)*7;
        const float* s1 = Wc + ((2*fp+1)*DIN + d)*7;
        float4* dst = &g_Wc2[(d*16 + fp)*4];
        dst[0] = make_float4(s0[0], s1[0], s0[1], s1[1]);
        dst[1] = make_float4(s0[2], s1[2], s0[3], s1[3]);
        dst[2] = make_float4(s0[4], s1[4], s0[5], s1[5]);
        dst[3] = make_float4(s0[6], s1[6], 0.0f, 0.0f);
    }
    if (idx < 128) {
        int fp = idx >> 3, o = idx & 7;
        g_bc2[idx] = (o < 7) ? make_float2(bc[(2*fp)*7 + o], bc[(2*fp+1)*7 + o])
                             : make_float2(0.0f, 0.0f);
    }
}

__device__ __forceinline__ u64 pack2(float lo, float hi) {
    u64 r; asm("mov.b64 %0, {%1, %2};" : "=l"(r) : "f"(lo), "f"(hi)); return r;
}
__device__ __forceinline__ float2 unpack2(u64 v) {
    float2 r; asm("mov.b64 {%0, %1}, %2;" : "=f"(r.x), "=f"(r.y) : "l"(v)); return r;
}
__device__ __forceinline__ void fma2(u64 &d, u64 a, u64 b) {
    asm("fma.rn.f32x2 %0, %1, %2, %0;" : "+l"(d) : "l"(a), "l"(b));
}

// -log(u), accurate near u->1 where __logf's absolute error would be amplified.
__device__ __forceinline__ float neg_log_u(float u) {
    float v = 1.0f - u;
    if (v < 0.0078125f)
        return v*(1.0f + v*(0.5f + v*(1.0f/3.0f)));
    return -__logf(u);
}

__global__ __launch_bounds__(NTHREADS, 3)
void hivae_kernel(const float* __restrict__ y,   const float* __restrict__ s,
                  const float* __restrict__ st,  const float* __restrict__ bz,
                  const float* __restrict__ br,  const float* __restrict__ eps,
                  const float* __restrict__ gum, const int* __restrict__ miss,
                  float* __restrict__ out)
{
    extern __shared__ float sm[];
    float* smT = sm + TSE_OFF;
    char*  smc = (char*)sm + MISS_BYTE_OFF;
    const int tid = threadIdx.x;
    const int rb  = blockIdx.x * ROWS;
    const int warp = tid >> 5, lane = tid & 31;

    // ---------------- stage YS (transposed), miss, lp ----------------------
    for (int idx = tid; idx < ROWS*DIN; idx += NTHREADS) {
        int row = idx >> 7, c = idx & 127;
        float v = (c < 64) ? y[(rb+row)*64 + c] : s[(rb+row)*64 + (c-64)];
        sm[YS_OFF + c*65 + row] = v;
    }
    for (int idx = tid; idx < ROWS*64; idx += NTHREADS) {
        int row = idx >> 6, c = idx & 63;
        smc[c*68 + row] = (char)miss[(rb+row)*64 + c];
    }
    if (tid < ROWS) sm[LP_OFF + tid] = 0.0f;
    __syncthreads();

    float lpc[4] = {0.f, 0.f, 0.f, 0.f};   // cat log-p per (h, q)

    // =========== categorical: jj groups of 16 contiguous features ==========
    #pragma unroll 1
    for (int jj = 0; jj < 2; jj++) {
        // GEMV: thread owns rows (lane, lane+32), feature pair fp = jj*8+warp
        const int fp = jj*8 + warp;
        u64 acc[2][7];
        {
            const float2* bp = &g_bc2[fp*8];
            #pragma unroll
            for (int o = 0; o < 7; o++) {
                float2 b = bp[o];
                u64 v = pack2(b.x, b.y);
                acc[0][o] = v; acc[1][o] = v;
            }
        }
        #pragma unroll 4
        for (int d = 0; d < DIN; d++) {
            float a0 = sm[YS_OFF + d*65 + lane];
            float a1 = sm[YS_OFF + d*65 + lane + 32];
            u64 A0 = pack2(a0, a0), A1 = pack2(a1, a1);
            const ulonglong2* wp = (const ulonglong2*)&g_Wc2[(d*16 + fp)*4];
            ulonglong2 w0 = wp[0], w1 = wp[1], w2 = wp[2];
            u64 w6 = *(const u64*)(wp + 3);
            fma2(acc[0][0], A0, w0.x); fma2(acc[1][0], A1, w0.x);
            fma2(acc[0][1], A0, w0.y); fma2(acc[1][1], A1, w0.y);
            fma2(acc[0][2], A0, w1.x); fma2(acc[1][2], A1, w1.x);
            fma2(acc[0][3], A0, w1.y); fma2(acc[1][3], A1, w1.y);
            fma2(acc[0][4], A0, w2.x); fma2(acc[1][4], A1, w2.x);
            fma2(acc[0][5], A0, w2.y); fma2(acc[1][5], A1, w2.y);
            fma2(acc[0][6], A0, w6);   fma2(acc[1][6], A1, w6);
        }

        // row-half chunks: transpose logits -> coalesced epilogue
        #pragma unroll 1
        for (int h = 0; h < 2; h++) {
            {   // write T: T[rloc*129 + fslot*8 + 1+o]
                int base = lane*129 + (warp*2)*8;
                #pragma unroll
                for (int o = 0; o < 7; o++) {
                    float2 v = unpack2(acc[h][o]);
                    smT[base + 1 + o]     = v.x;
                    smT[base + 8 + 1 + o] = v.y;
                }
            }
            __syncthreads();
            #pragma unroll
            for (int q = 0; q < 2; q++) {
                const int fslot = tid & 15;
                const int rloc  = (tid >> 4) + 16*q;
                const int f     = jj*16 + fslot;
                const int r     = h*32 + rloc;
                const int grow  = rb + r;
                // coalesced loads first (MLP)
                const float4* gu = (const float4*)(gum + (size_t)grow*256 + f*8);
                float4 g0 = gu[0], g1 = gu[1];
                const float4* dc = (const float4*)(st + (size_t)grow*288 + 32 + f*8);
                float4 d0 = dc[0], d1 = dc[1];
                float missf = (float)smc[(32+f)*68 + r];

                float lpi[8];
                lpi[0] = 0.0f;
                const int tb = rloc*129 + fslot*8;
                #pragma unroll
                for (int k = 1; k < 8; k++) lpi[k] = smT[tb + k];

                float m = lpi[0];
                #pragma unroll
                for (int k = 1; k < 8; k++) m = fmaxf(m, lpi[k]);
                float se = 0.0f;
                #pragma unroll
                for (int k = 0; k < 8; k++) se += __expf(lpi[k] - m);
                float lse = m + __logf(se);

                float lp = d0.x*(lpi[0]-lse) + d0.y*(lpi[1]-lse) + d0.z*(lpi[2]-lse) + d0.w*(lpi[3]-lse)
                         + d1.x*(lpi[4]-lse) + d1.y*(lpi[5]-lse) + d1.z*(lpi[6]-lse) + d1.w*(lpi[7]-lse);
                lpc[h*2 + q] += lp * missf;

                float uv[8] = {g0.x,g0.y,g0.z,g0.w,g1.x,g1.y,g1.z,g1.w};
                float best = -1e30f; int bi = 0;
                #pragma unroll
                for (int k = 0; k < 8; k++) {
                    float u  = fminf(fmaxf(uv[k], 1e-6f), 1.0f - 1e-6f);
                    float gk = -__logf(neg_log_u(u));
                    float val = lpi[k] + gk;
                    if (val > best) { best = val; bi = k; }
                }
                sm[SAMP_OFF + r*65 + 32 + f] = (float)bi;
            }
            __syncthreads();
        }
    }
    // commit cat log-p (rows fixed per (h,q) across jj)
    #pragma unroll
    for (int h = 0; h < 2; h++)
        #pragma unroll
        for (int q = 0; q < 2; q++)
            atomicAdd(&sm[LP_OFF + h*32 + (tid >> 4) + 16*q], lpc[h*2 + q]);

    // ------------- stage st/eps (region reuse after T is dead) -------------
    for (int idx = tid; idx < ROWS*32; idx += NTHREADS) {
        int row = idx >> 5, c = idx & 31;
        sm[ST2_OFF  + c*65 + row] = st[(rb+row)*288 + c];
        sm[EPS2_OFF + c*65 + row] = eps[(rb+row)*32 + c];
    }
    __syncthreads();

    // =========== real: 4 features x 2 rows, (mean,logvar) packed ===========
    {
        const int f0 = warp*4;
        u64 ar[2][4];
        {
            float4 b0 = *(const float4*)&br[f0*2];
            float4 b1 = *(const float4*)&br[f0*2 + 4];
            ar[0][0] = ar[1][0] = pack2(b0.x, b0.y);
            ar[0][1] = ar[1][1] = pack2(b0.z, b0.w);
            ar[0][2] = ar[1][2] = pack2(b1.x, b1.y);
            ar[0][3] = ar[1][3] = pack2(b1.z, b1.w);
        }
        #pragma unroll 4
        for (int d = 0; d < DIN; d++) {
            float a0 = sm[YS_OFF + d*65 + lane];
            float a1 = sm[YS_OFF + d*65 + lane + 32];
            u64 A0 = pack2(a0, a0), A1 = pack2(a1, a1);
            ulonglong2 wA = *(const ulonglong2*)&g_Wr2[d*32 + f0];
            ulonglong2 wB = *(const ulonglong2*)&g_Wr2[d*32 + f0 + 2];
            fma2(ar[0][0], A0, wA.x); fma2(ar[1][0], A1, wA.x);
            fma2(ar[0][1], A0, wA.y); fma2(ar[1][1], A1, wA.y);
            fma2(ar[0][2], A0, wB.x); fma2(ar[1][2], A1, wB.x);
            fma2(ar[0][3], A0, wB.y); fma2(ar[1][3], A1, wB.y);
        }
        float lp0 = 0.f, lp1 = 0.f;
        #pragma unroll
        for (int i = 0; i < 2; i++) {
            const int r = i*32 + lane;
            #pragma unroll
            for (int qf = 0; qf < 4; qf++) {
                const int f = f0 + qf;
                float2 mv = unpack2(ar[i][qf]);
                float mu = mv.x;
                float lv = fminf(fmaxf(mv.y, -10.0f), 10.0f);
                float x  = sm[ST2_OFF + f*65 + r];
                float mi = (float)smc[f*68 + r];
                float dmu = x - mu;
                float lp = (-0.5f*dmu*dmu*__expf(-lv) - 0.5f*lv - HALF_LOG2PI) * mi;
                if (i == 0) lp0 += lp; else lp1 += lp;
                float sd = fmaxf(__expf(0.5f*lv), 1e-6f);
                sm[SAMP_OFF + r*65 + f] = mu + sd * sm[EPS2_OFF + f*65 + r];
            }
        }
        atomicAdd(&sm[LP_OFF + lane],      lp0);
        atomicAdd(&sm[LP_OFF + lane + 32], lp1);
    }

    // =========== mean_pz: 8 z-outputs x 2 rows, z-pairs packed =============
    {
        const int zb = warp*8;
        const long B64 = (long)B_TOT*64;
        u64 az[2][4];
        {
            float4 b0 = *(const float4*)&bz[zb];
            float4 b1 = *(const float4*)&bz[zb + 4];
            az[0][0] = az[1][0] = pack2(b0.x, b0.y);
            az[0][1] = az[1][1] = pack2(b0.z, b0.w);
            az[0][2] = az[1][2] = pack2(b1.x, b1.y);
            az[0][3] = az[1][3] = pack2(b1.z, b1.w);
        }
        #pragma unroll 4
        for (int d = 0; d < SDIM; d++) {
            float a0 = sm[YS_OFF + (64+d)*65 + lane];
            float a1 = sm[YS_OFF + (64+d)*65 + lane + 32];
            u64 A0 = pack2(a0, a0), A1 = pack2(a1, a1);
            ulonglong2 w0 = *(const ulonglong2*)&g_Wzt[d*64 + zb];
            ulonglong2 w1 = *(const ulonglong2*)&g_Wzt[d*64 + zb + 4];
            fma2(az[0][0], A0, w0.x); fma2(az[1][0], A1, w0.x);
            fma2(az[0][1], A0, w0.y); fma2(az[1][1], A1, w0.y);
            fma2(az[0][2], A0, w1.x); fma2(az[1][2], A1, w1.x);
            fma2(az[0][3], A0, w1.y); fma2(az[1][3], A1, w1.y);
        }
        #pragma unroll
        for (int i = 0; i < 2; i++) {
            const long grow = rb + i*32 + lane;
            float2 p0 = unpack2(az[i][0]), p1 = unpack2(az[i][1]);
            float2 p2 = unpack2(az[i][2]), p3 = unpack2(az[i][3]);
            *(float4*)&out[B64 + grow*64 + zb]     = make_float4(p0.x, p0.y, p1.x, p1.y);
            *(float4*)&out[B64 + grow*64 + zb + 4] = make_float4(p2.x, p2.y, p3.x, p3.y);
        }
    }

    __syncthreads();

    // -------- coalesced stores: samples, zeros, log_p_sum -------------------
    const long B64 = (long)B_TOT*64;
    const float4 z4 = make_float4(0.f,0.f,0.f,0.f);
    for (int idx = tid; idx < ROWS*16; idx += NTHREADS) {
        int row = idx >> 4, c = (idx & 15)*4;
        long g = (long)(rb+row)*64 + c;
        float4 v = make_float4(sm[SAMP_OFF + row*65 + c],
                               sm[SAMP_OFF + row*65 + c + 1],
                               sm[SAMP_OFF + row*65 + c + 2],
                               sm[SAMP_OFF + row*65 + c + 3]);
        *(float4*)&out[g] = v;
        *(float4*)&out[2*B64 + g] = z4;
    }
    if (tid < ROWS) out[3*B64 + rb + tid] = sm[LP_OFF + tid];
}

extern "C" void kernel_launch(void* const* d_in, const int* in_sizes, int n_in,
                              void* d_out, int out_size)
{
    const float* y    = (const float*)d_in[0];
    const float* s    = (const float*)d_in[1];
    const float* st   = (const float*)d_in[2];
    const float* Wz   = (const float*)d_in[3];
    const float* bz   = (const float*)d_in[4];
    const float* Wr   = (const float*)d_in[5];
    const float* br   = (const float*)d_in[6];
    const float* Wc   = (const float*)d_in[7];
    const float* bc   = (const float*)d_in[8];
    const float* eps  = (const float*)d_in[9];
    const float* gum  = (const float*)d_in[10];
    const int*   miss = (const int*)d_in[11];
    float* out = (float*)d_out;

    cudaFuncSetAttribute(hivae_kernel,
                         cudaFuncAttributeMaxDynamicSharedMemorySize, SMEM_BYTES);
    repack_kernel<<<16, 256>>>(Wc, Wr, Wz, bc);
    hivae_kernel<<<B_TOT/ROWS, NTHREADS, SMEM_BYTES>>>(
        y, s, st, bz, br, eps, gum, miss, out);
}